// round 7
// baseline (speedup 1.0000x reference)
#include <cuda_runtime.h>
#include <cuda_fp16.h>
#include <math.h>
#include <stdint.h>

// Problem shape (fixed by the reference)
#define BQ 64
#define SQ 197
#define DQ 768
#define HQ 3072
#define MQ (BQ * SQ)  // 12608

// ---------------------------------------------------------------------------
// Device global scratch (no allocation allowed)
// ---------------------------------------------------------------------------
__device__ __half g_xh [(size_t)MQ * DQ];   // x in fp16
__device__ __half g_hh [(size_t)MQ * HQ];   // h (post-GELU) in fp16
__device__ __half g_q1 [(size_t)HQ * DQ];   // ternary w1 in fp16 (exact)
__device__ __half g_q2 [(size_t)DQ * HQ];   // ternary w2 in fp16 (exact)
__device__ float g_partial[1024];
__device__ float g_gamma[2];

__device__ __forceinline__ uint32_t smem_u32(const void* p) {
    uint32_t a;
    asm("{ .reg .u64 t; cvta.to.shared.u64 t, %1; cvt.u32.u64 %0, t; }"
        : "=r"(a) : "l"(p));
    return a;
}

// ---------------------------------------------------------------------------
// Prep kernels
// ---------------------------------------------------------------------------
__global__ void abs_sum_kernel(const float* __restrict__ w, int n, int slot) {
    __shared__ float sdata[256];
    float s = 0.0f;
    for (int i = blockIdx.x * blockDim.x + threadIdx.x; i < n;
         i += gridDim.x * blockDim.x)
        s += fabsf(w[i]);
    sdata[threadIdx.x] = s;
    __syncthreads();
    #pragma unroll
    for (int off = 128; off > 0; off >>= 1) {
        if (threadIdx.x < off) sdata[threadIdx.x] += sdata[threadIdx.x + off];
        __syncthreads();
    }
    if (threadIdx.x == 0) g_partial[slot * 512 + blockIdx.x] = sdata[0];
}

__global__ void finalize_gamma_kernel(int n1, int n2) {
    __shared__ float sdata[512];
    int t = threadIdx.x;
    sdata[t] = g_partial[t];
    __syncthreads();
    #pragma unroll
    for (int off = 256; off > 0; off >>= 1) {
        if (t < off) sdata[t] += sdata[t + off];
        __syncthreads();
    }
    if (t == 0) g_gamma[0] = sdata[0] / (float)n1 + 1e-5f;
    __syncthreads();
    sdata[t] = g_partial[512 + t];
    __syncthreads();
    #pragma unroll
    for (int off = 256; off > 0; off >>= 1) {
        if (t < off) sdata[t] += sdata[t + off];
        __syncthreads();
    }
    if (t == 0) g_gamma[1] = sdata[0] / (float)n2 + 1e-5f;
}

// ternarize to fp16 (4 per thread); q in {-1,0,1} exact in fp16
__global__ void quant_h_kernel(const float* __restrict__ w,
                               __half* __restrict__ q, int n4, int slot) {
    int i = blockIdx.x * blockDim.x + threadIdx.x;
    if (i >= n4) return;
    float inv = 1.0f / g_gamma[slot];
    float4 v = ((const float4*)w)[i];
    __half2 o0, o1;
    o0.x = __float2half_rn(fminf(1.0f, fmaxf(-1.0f, rintf(v.x * inv))));
    o0.y = __float2half_rn(fminf(1.0f, fmaxf(-1.0f, rintf(v.y * inv))));
    o1.x = __float2half_rn(fminf(1.0f, fmaxf(-1.0f, rintf(v.z * inv))));
    o1.y = __float2half_rn(fminf(1.0f, fmaxf(-1.0f, rintf(v.w * inv))));
    ((__half2*)q)[2 * i + 0] = o0;
    ((__half2*)q)[2 * i + 1] = o1;
}

// x fp32 -> fp16 (4 per thread)
__global__ void cvt_h_kernel(const float* __restrict__ x,
                             __half* __restrict__ xh, int n4) {
    int i = blockIdx.x * blockDim.x + threadIdx.x;
    if (i >= n4) return;
    float4 v = ((const float4*)x)[i];
    __half2 o0, o1;
    o0.x = __float2half_rn(v.x); o0.y = __float2half_rn(v.y);
    o1.x = __float2half_rn(v.z); o1.y = __float2half_rn(v.w);
    ((__half2*)xh)[2 * i + 0] = o0;
    ((__half2*)xh)[2 * i + 1] = o1;
}

// ---------------------------------------------------------------------------
// HMMA GEMM: C[M,N] = epi( gamma * (A[M,K] @ B[N,K]^T) + bias[N] )
//   A,B fp16 row-major (K contiguous). 128x128 CTA tile, 8 warps, each warp
//   64x32 via mma.sync.m16n8k16. Swizzled SMEM, 3-stage cp.async pipeline,
//   ONE __syncthreads per chunk (load of c+2 after the barrier is hazard-free:
//   it writes stage (c-1)%3, which all warps finished reading in compute(c-1)).
// ---------------------------------------------------------------------------
template <int GELU_H>
__global__ __launch_bounds__(256, 2)
void hmma_gemm(const __half* __restrict__ A,
               const __half* __restrict__ B,
               const float* __restrict__ bias,
               void* __restrict__ Cout,
               int M, int N, int K, int gslot) {
    extern __shared__ char smem[];
    const uint32_t sb = smem_u32(smem);
    const int tid  = threadIdx.x;
    const int wid  = tid >> 5;
    const int lane = tid & 31;
    const int m0 = blockIdx.y * 128;
    const int n0 = blockIdx.x * 128;
    const int wm = wid & 1;    // 2 m-blocks of 64
    const int wn = wid >> 1;   // 4 n-blocks of 32

    const int nch = K >> 6;    // chunks of 64 fp16

    float acc[4][4][4];
    #pragma unroll
    for (int i = 0; i < 4; i++)
        #pragma unroll
        for (int j = 0; j < 4; j++)
            #pragma unroll
            for (int k = 0; k < 4; k++) acc[i][j][k] = 0.0f;

    // ---- chunk loader (cp.async, zfill on M edge); stage = 32KB ----
    auto load_chunk = [&](int c) {
        const uint32_t base = (uint32_t)(c % 3) * 32768u;
        const uint32_t offB = base + 16384u;
        const __half* Ag = A + (size_t)m0 * K + (size_t)c * 64;
        const __half* Bg = B + (size_t)n0 * K + (size_t)c * 64;
        #pragma unroll
        for (int t = 0; t < 4; t++) {
            int idx = tid + t * 256;            // 0..1023
            int row = idx >> 3;
            int c16 = idx & 7;
            uint32_t bo = (uint32_t)row * 128u + (uint32_t)c16 * 16u;
            uint32_t sw = bo ^ ((bo >> 3) & 0x70u);
            const void* ga = Ag + (size_t)row * K + c16 * 8;
            uint32_t na = (m0 + row < M) ? 16u : 0u;
            asm volatile("cp.async.cg.shared.global [%0], [%1], 16, %2;"
                         :: "r"(sb + base + sw), "l"(ga), "r"(na));
            const void* gb = Bg + (size_t)row * K + c16 * 8;
            asm volatile("cp.async.cg.shared.global [%0], [%1], 16;"
                         :: "r"(sb + offB + sw), "l"(gb));
        }
        asm volatile("cp.async.commit_group;" ::: "memory");
    };

    // ---- compute one chunk from stage stg ----
    auto compute_chunk = [&](int stg) {
        const uint32_t offA = sb + (uint32_t)stg * 32768u;
        const uint32_t offB = offA + 16384u;
        #pragma unroll
        for (int kk = 0; kk < 64; kk += 16) {
            uint32_t a[4][4];
            #pragma unroll
            for (int mi = 0; mi < 4; mi++) {
                int r = wm * 64 + mi * 16 + (lane & 15);
                uint32_t bo = (uint32_t)r * 128u
                            + (uint32_t)(kk + ((lane >> 4) << 3)) * 2u;
                uint32_t sw = bo ^ ((bo >> 3) & 0x70u);
                asm volatile(
                    "ldmatrix.sync.aligned.m8n8.x4.shared.b16 {%0,%1,%2,%3}, [%4];"
                    : "=r"(a[mi][0]), "=r"(a[mi][1]), "=r"(a[mi][2]), "=r"(a[mi][3])
                    : "r"(offA + sw));
            }
            uint32_t b[4][2];
            #pragma unroll
            for (int nj = 0; nj < 2; nj++) {
                int r = wn * 32 + nj * 16 + (lane & 7) + ((lane >> 4) << 3);
                uint32_t bo = (uint32_t)r * 128u
                            + (uint32_t)(kk + (lane & 8)) * 2u;
                uint32_t sw = bo ^ ((bo >> 3) & 0x70u);
                uint32_t b0, b1, b2, b3;
                asm volatile(
                    "ldmatrix.sync.aligned.m8n8.x4.shared.b16 {%0,%1,%2,%3}, [%4];"
                    : "=r"(b0), "=r"(b1), "=r"(b2), "=r"(b3)
                    : "r"(offB + sw));
                b[nj * 2 + 0][0] = b0; b[nj * 2 + 0][1] = b1;
                b[nj * 2 + 1][0] = b2; b[nj * 2 + 1][1] = b3;
            }
            #pragma unroll
            for (int mi = 0; mi < 4; mi++)
                #pragma unroll
                for (int ni = 0; ni < 4; ni++)
                    asm volatile(
                        "mma.sync.aligned.m16n8k16.row.col.f32.f16.f16.f32 "
                        "{%0,%1,%2,%3}, {%4,%5,%6,%7}, {%8,%9}, {%0,%1,%2,%3};"
                        : "+f"(acc[mi][ni][0]), "+f"(acc[mi][ni][1]),
                          "+f"(acc[mi][ni][2]), "+f"(acc[mi][ni][3])
                        : "r"(a[mi][0]), "r"(a[mi][1]), "r"(a[mi][2]), "r"(a[mi][3]),
                          "r"(b[ni][0]), "r"(b[ni][1]));
        }
    };

    load_chunk(0);
    load_chunk(1);
    for (int c = 0; c < nch; c++) {
        if (c == nch - 1)
            asm volatile("cp.async.wait_group 0;" ::: "memory");
        else
            asm volatile("cp.async.wait_group 1;" ::: "memory");
        __syncthreads();
        if (c + 2 < nch) load_chunk(c + 2);
        compute_chunk(c % 3);
    }

    // ---- epilogue: gamma * acc + bias (+ exact GELU -> fp16) ----
    const float gamma = g_gamma[gslot];
    #pragma unroll
    for (int mi = 0; mi < 4; mi++) {
        #pragma unroll
        for (int half = 0; half < 2; half++) {
            int gr = m0 + wm * 64 + mi * 16 + (lane >> 2) + half * 8;
            if (gr >= M) continue;
            #pragma unroll
            for (int ni = 0; ni < 4; ni++) {
                int gc = n0 + wn * 32 + ni * 8 + 2 * (lane & 3);
                float v0 = acc[mi][ni][half * 2 + 0] * gamma + bias[gc];
                float v1 = acc[mi][ni][half * 2 + 1] * gamma + bias[gc + 1];
                if (GELU_H) {
                    v0 = 0.5f * v0 * (1.0f + erff(v0 * 0.70710678118654752f));
                    v1 = 0.5f * v1 * (1.0f + erff(v1 * 0.70710678118654752f));
                    __half2 p;
                    p.x = __float2half_rn(v0);
                    p.y = __float2half_rn(v1);
                    *(__half2*)((__half*)Cout + (size_t)gr * N + gc) = p;
                } else {
                    *(float2*)((float*)Cout + (size_t)gr * N + gc) =
                        make_float2(v0, v1);
                }
            }
        }
    }
}

// ---------------------------------------------------------------------------
// Launch
// ---------------------------------------------------------------------------
extern "C" void kernel_launch(void* const* d_in, const int* in_sizes, int n_in,
                              void* d_out, int out_size) {
    const float* x  = (const float*)d_in[0];
    const float* w1 = (const float*)d_in[1];
    const float* b1 = (const float*)d_in[2];
    const float* w2 = (const float*)d_in[3];
    const float* b2 = (const float*)d_in[4];
    float* out = (float*)d_out;

    __half *p_xh, *p_hh, *p_q1, *p_q2;
    cudaGetSymbolAddress((void**)&p_xh, g_xh);
    cudaGetSymbolAddress((void**)&p_hh, g_hh);
    cudaGetSymbolAddress((void**)&p_q1, g_q1);
    cudaGetSymbolAddress((void**)&p_q2, g_q2);

    const int NW = HQ * DQ;          // 2359296
    const int NX = MQ * DQ;          // 9682944
    const int SMEM_DYN = 3 * 32768;  // 96KB: 3 stages x (A 16K + B 16K)

    static bool attr_done = false;
    if (!attr_done) {
        cudaFuncSetAttribute(hmma_gemm<1>,
            cudaFuncAttributeMaxDynamicSharedMemorySize, SMEM_DYN);
        cudaFuncSetAttribute(hmma_gemm<0>,
            cudaFuncAttributeMaxDynamicSharedMemorySize, SMEM_DYN);
        attr_done = true;
    }

    abs_sum_kernel<<<512, 256>>>(w1, NW, 0);
    abs_sum_kernel<<<512, 256>>>(w2, NW, 1);
    finalize_gamma_kernel<<<1, 512>>>(NW, NW);

    quant_h_kernel<<<(NW / 4 + 255) / 256, 256>>>(w1, p_q1, NW / 4, 0);
    quant_h_kernel<<<(NW / 4 + 255) / 256, 256>>>(w2, p_q2, NW / 4, 1);
    cvt_h_kernel<<<(NX / 4 + 255) / 256, 256>>>(x, p_xh, NX / 4);

    // GEMM1: [M, 768] x [H, 768]^T -> gelu -> fp16 h
    {
        dim3 grid(HQ / 128, (MQ + 127) / 128);
        hmma_gemm<1><<<grid, 256, SMEM_DYN>>>(
            p_xh, p_q1, b1, (void*)p_hh, MQ, HQ, DQ, 0);
    }
    // GEMM2: [M, 3072] x [D, 3072]^T -> + b2 -> out fp32
    {
        dim3 grid(DQ / 128, (MQ + 127) / 128);
        hmma_gemm<0><<<grid, 256, SMEM_DYN>>>(
            p_hh, p_q2, b2, (void*)out, MQ, DQ, HQ, 1);
    }
}

// round 8
// speedup vs baseline: 1.0916x; 1.0916x over previous
#include <cuda_runtime.h>
#include <cuda_fp16.h>
#include <math.h>
#include <stdint.h>

// Problem shape (fixed by the reference)
#define BQ 64
#define SQ 197
#define DQ 768
#define HQ 3072
#define MQ (BQ * SQ)  // 12608

// ---------------------------------------------------------------------------
// Device global scratch (no allocation allowed)
// ---------------------------------------------------------------------------
__device__ __half g_xh [(size_t)MQ * DQ];   // x in fp16
__device__ __half g_hh [(size_t)MQ * HQ];   // h (post-GELU) in fp16
__device__ __half g_q1 [(size_t)HQ * DQ];   // ternary w1 in fp16 (exact)
__device__ __half g_q2 [(size_t)DQ * HQ];   // ternary w2 in fp16 (exact)
__device__ float g_partial[1024];
__device__ float g_gamma[2];

__device__ __forceinline__ uint32_t smem_u32(const void* p) {
    uint32_t a;
    asm("{ .reg .u64 t; cvta.to.shared.u64 t, %1; cvt.u32.u64 %0, t; }"
        : "=r"(a) : "l"(p));
    return a;
}

// ---------------------------------------------------------------------------
// Prep kernels
// ---------------------------------------------------------------------------
__global__ void abs_sum_kernel(const float* __restrict__ w, int n, int slot) {
    __shared__ float sdata[256];
    float s = 0.0f;
    for (int i = blockIdx.x * blockDim.x + threadIdx.x; i < n;
         i += gridDim.x * blockDim.x)
        s += fabsf(w[i]);
    sdata[threadIdx.x] = s;
    __syncthreads();
    #pragma unroll
    for (int off = 128; off > 0; off >>= 1) {
        if (threadIdx.x < off) sdata[threadIdx.x] += sdata[threadIdx.x + off];
        __syncthreads();
    }
    if (threadIdx.x == 0) g_partial[slot * 512 + blockIdx.x] = sdata[0];
}

__global__ void finalize_gamma_kernel(int n1, int n2) {
    __shared__ float sdata[512];
    int t = threadIdx.x;
    sdata[t] = g_partial[t];
    __syncthreads();
    #pragma unroll
    for (int off = 256; off > 0; off >>= 1) {
        if (t < off) sdata[t] += sdata[t + off];
        __syncthreads();
    }
    if (t == 0) g_gamma[0] = sdata[0] / (float)n1 + 1e-5f;
    __syncthreads();
    sdata[t] = g_partial[512 + t];
    __syncthreads();
    #pragma unroll
    for (int off = 256; off > 0; off >>= 1) {
        if (t < off) sdata[t] += sdata[t + off];
        __syncthreads();
    }
    if (t == 0) g_gamma[1] = sdata[0] / (float)n2 + 1e-5f;
}

// ternarize BOTH weights to fp16 in one launch (4 elems per thread)
__global__ void quant_both_kernel(const float* __restrict__ w1,
                                  __half* __restrict__ q1,
                                  const float* __restrict__ w2,
                                  __half* __restrict__ q2, int n4) {
    int i = blockIdx.x * blockDim.x + threadIdx.x;
    if (i >= 2 * n4) return;
    const float* w;
    __half* q;
    int slot, j;
    if (i < n4) { w = w1; q = q1; slot = 0; j = i; }
    else        { w = w2; q = q2; slot = 1; j = i - n4; }
    float inv = 1.0f / g_gamma[slot];
    float4 v = ((const float4*)w)[j];
    __half2 o0, o1;
    o0.x = __float2half_rn(fminf(1.0f, fmaxf(-1.0f, rintf(v.x * inv))));
    o0.y = __float2half_rn(fminf(1.0f, fmaxf(-1.0f, rintf(v.y * inv))));
    o1.x = __float2half_rn(fminf(1.0f, fmaxf(-1.0f, rintf(v.z * inv))));
    o1.y = __float2half_rn(fminf(1.0f, fmaxf(-1.0f, rintf(v.w * inv))));
    ((__half2*)q)[2 * j + 0] = o0;
    ((__half2*)q)[2 * j + 1] = o1;
}

// x fp32 -> fp16 (4 per thread)
__global__ void cvt_h_kernel(const float* __restrict__ x,
                             __half* __restrict__ xh, int n4) {
    int i = blockIdx.x * blockDim.x + threadIdx.x;
    if (i >= n4) return;
    float4 v = ((const float4*)x)[i];
    __half2 o0, o1;
    o0.x = __float2half_rn(v.x); o0.y = __float2half_rn(v.y);
    o1.x = __float2half_rn(v.z); o1.y = __float2half_rn(v.w);
    ((__half2*)xh)[2 * i + 0] = o0;
    ((__half2*)xh)[2 * i + 1] = o1;
}

// ---------------------------------------------------------------------------
// HMMA GEMM (R5 engine, unchanged): C = epi(gamma * (A @ B^T) + bias)
//   128x128 CTA tile, 8 warps x (64x32), m16n8k16, swizzled SMEM,
//   double-buffered cp.async.
// ---------------------------------------------------------------------------
template <int GELU_H>
__global__ __launch_bounds__(256, 2)
void hmma_gemm(const __half* __restrict__ A,
               const __half* __restrict__ B,
               const float* __restrict__ bias,
               void* __restrict__ Cout,
               int M, int N, int K, int gslot) {
    extern __shared__ char smem[];
    const uint32_t sb = smem_u32(smem);
    const int tid  = threadIdx.x;
    const int wid  = tid >> 5;
    const int lane = tid & 31;
    const int m0 = blockIdx.y * 128;
    const int n0 = blockIdx.x * 128;
    const int wm = wid & 1;    // 2 m-blocks of 64
    const int wn = wid >> 1;   // 4 n-blocks of 32

    const int nch = K >> 6;    // chunks of 64 fp16

    float acc[4][4][4];
    #pragma unroll
    for (int i = 0; i < 4; i++)
        #pragma unroll
        for (int j = 0; j < 4; j++)
            #pragma unroll
            for (int k = 0; k < 4; k++) acc[i][j][k] = 0.0f;

    auto load_chunk = [&](int c) {
        const int buf = c & 1;
        const uint32_t offA = buf * 32768u;
        const uint32_t offB = offA + 16384u;
        const __half* Ag = A + (size_t)m0 * K + (size_t)c * 64;
        const __half* Bg = B + (size_t)n0 * K + (size_t)c * 64;
        #pragma unroll
        for (int t = 0; t < 4; t++) {
            int idx = tid + t * 256;            // 0..1023
            int row = idx >> 3;
            int c16 = idx & 7;
            uint32_t bo = (uint32_t)row * 128u + (uint32_t)c16 * 16u;
            uint32_t sw = bo ^ ((bo >> 3) & 0x70u);
            const void* ga = Ag + (size_t)row * K + c16 * 8;
            uint32_t na = (m0 + row < M) ? 16u : 0u;
            asm volatile("cp.async.cg.shared.global [%0], [%1], 16, %2;"
                         :: "r"(sb + offA + sw), "l"(ga), "r"(na));
            const void* gb = Bg + (size_t)row * K + c16 * 8;
            asm volatile("cp.async.cg.shared.global [%0], [%1], 16;"
                         :: "r"(sb + offB + sw), "l"(gb));
        }
        asm volatile("cp.async.commit_group;" ::: "memory");
    };

    auto compute_chunk = [&](int buf) {
        const uint32_t offA = buf * 32768u;
        const uint32_t offB = offA + 16384u;
        #pragma unroll
        for (int kk = 0; kk < 64; kk += 16) {
            uint32_t a[4][4];
            #pragma unroll
            for (int mi = 0; mi < 4; mi++) {
                int r = wm * 64 + mi * 16 + (lane & 15);
                uint32_t bo = (uint32_t)r * 128u
                            + (uint32_t)(kk + ((lane >> 4) << 3)) * 2u;
                uint32_t sw = bo ^ ((bo >> 3) & 0x70u);
                asm volatile(
                    "ldmatrix.sync.aligned.m8n8.x4.shared.b16 {%0,%1,%2,%3}, [%4];"
                    : "=r"(a[mi][0]), "=r"(a[mi][1]), "=r"(a[mi][2]), "=r"(a[mi][3])
                    : "r"(sb + offA + sw));
            }
            uint32_t b[4][2];
            #pragma unroll
            for (int nj = 0; nj < 2; nj++) {
                int r = wn * 32 + nj * 16 + (lane & 7) + ((lane >> 4) << 3);
                uint32_t bo = (uint32_t)r * 128u
                            + (uint32_t)(kk + (lane & 8)) * 2u;
                uint32_t sw = bo ^ ((bo >> 3) & 0x70u);
                uint32_t b0, b1, b2, b3;
                asm volatile(
                    "ldmatrix.sync.aligned.m8n8.x4.shared.b16 {%0,%1,%2,%3}, [%4];"
                    : "=r"(b0), "=r"(b1), "=r"(b2), "=r"(b3)
                    : "r"(sb + offB + sw));
                b[nj * 2 + 0][0] = b0; b[nj * 2 + 0][1] = b1;
                b[nj * 2 + 1][0] = b2; b[nj * 2 + 1][1] = b3;
            }
            #pragma unroll
            for (int mi = 0; mi < 4; mi++)
                #pragma unroll
                for (int ni = 0; ni < 4; ni++)
                    asm volatile(
                        "mma.sync.aligned.m16n8k16.row.col.f32.f16.f16.f32 "
                        "{%0,%1,%2,%3}, {%4,%5,%6,%7}, {%8,%9}, {%0,%1,%2,%3};"
                        : "+f"(acc[mi][ni][0]), "+f"(acc[mi][ni][1]),
                          "+f"(acc[mi][ni][2]), "+f"(acc[mi][ni][3])
                        : "r"(a[mi][0]), "r"(a[mi][1]), "r"(a[mi][2]), "r"(a[mi][3]),
                          "r"(b[ni][0]), "r"(b[ni][1]));
        }
    };

    load_chunk(0);
    for (int c = 0; c < nch; c++) {
        if (c + 1 < nch) {
            load_chunk(c + 1);
            asm volatile("cp.async.wait_group 1;" ::: "memory");
        } else {
            asm volatile("cp.async.wait_group 0;" ::: "memory");
        }
        __syncthreads();
        compute_chunk(c & 1);
        __syncthreads();
    }

    // ---- epilogue: gamma * acc + bias (+ exact GELU -> fp16) ----
    const float gamma = g_gamma[gslot];
    #pragma unroll
    for (int mi = 0; mi < 4; mi++) {
        #pragma unroll
        for (int half = 0; half < 2; half++) {
            int gr = m0 + wm * 64 + mi * 16 + (lane >> 2) + half * 8;
            if (gr >= M) continue;
            #pragma unroll
            for (int ni = 0; ni < 4; ni++) {
                int gc = n0 + wn * 32 + ni * 8 + 2 * (lane & 3);
                float v0 = acc[mi][ni][half * 2 + 0] * gamma + bias[gc];
                float v1 = acc[mi][ni][half * 2 + 1] * gamma + bias[gc + 1];
                if (GELU_H) {
                    v0 = 0.5f * v0 * (1.0f + erff(v0 * 0.70710678118654752f));
                    v1 = 0.5f * v1 * (1.0f + erff(v1 * 0.70710678118654752f));
                    __half2 p;
                    p.x = __float2half_rn(v0);
                    p.y = __float2half_rn(v1);
                    *(__half2*)((__half*)Cout + (size_t)gr * N + gc) = p;
                } else {
                    *(float2*)((float*)Cout + (size_t)gr * N + gc) =
                        make_float2(v0, v1);
                }
            }
        }
    }
}

// ---------------------------------------------------------------------------
// Launch  (gemm1 is launch index 5 -> ncu -s 5 -c 1 captures it)
// ---------------------------------------------------------------------------
extern "C" void kernel_launch(void* const* d_in, const int* in_sizes, int n_in,
                              void* d_out, int out_size) {
    const float* x  = (const float*)d_in[0];
    const float* w1 = (const float*)d_in[1];
    const float* b1 = (const float*)d_in[2];
    const float* w2 = (const float*)d_in[3];
    const float* b2 = (const float*)d_in[4];
    float* out = (float*)d_out;

    __half *p_xh, *p_hh, *p_q1, *p_q2;
    cudaGetSymbolAddress((void**)&p_xh, g_xh);
    cudaGetSymbolAddress((void**)&p_hh, g_hh);
    cudaGetSymbolAddress((void**)&p_q1, g_q1);
    cudaGetSymbolAddress((void**)&p_q2, g_q2);

    const int NW = HQ * DQ;          // 2359296
    const int NX = MQ * DQ;          // 9682944
    const int SMEM_DYN = 2 * 32768;  // 64KB: 2 x (A 16K + B 16K)

    static bool attr_done = false;
    if (!attr_done) {
        cudaFuncSetAttribute(hmma_gemm<1>,
            cudaFuncAttributeMaxDynamicSharedMemorySize, SMEM_DYN);
        cudaFuncSetAttribute(hmma_gemm<0>,
            cudaFuncAttributeMaxDynamicSharedMemorySize, SMEM_DYN);
        attr_done = true;
    }

    abs_sum_kernel<<<512, 256>>>(w1, NW, 0);                       // 0
    abs_sum_kernel<<<512, 256>>>(w2, NW, 1);                       // 1
    finalize_gamma_kernel<<<1, 512>>>(NW, NW);                     // 2
    quant_both_kernel<<<(2 * (NW / 4) + 255) / 256, 256>>>(        // 3
        w1, p_q1, w2, p_q2, NW / 4);
    cvt_h_kernel<<<(NX / 4 + 255) / 256, 256>>>(x, p_xh, NX / 4);  // 4

    // GEMM1 (launch 5): [M, 768] x [H, 768]^T -> gelu -> fp16 h
    {
        dim3 grid(HQ / 128, (MQ + 127) / 128);
        hmma_gemm<1><<<grid, 256, SMEM_DYN>>>(
            p_xh, p_q1, b1, (void*)p_hh, MQ, HQ, DQ, 0);
    }
    // GEMM2 (launch 6): [M, 3072] x [D, 3072]^T -> + b2 -> out fp32
    {
        dim3 grid(DQ / 128, (MQ + 127) / 128);
        hmma_gemm<0><<<grid, 256, SMEM_DYN>>>(
            p_hh, p_q2, b2, (void*)out, MQ, DQ, HQ, 1);
    }
}